// round 2
// baseline (speedup 1.0000x reference)
#include <cuda_runtime.h>
#include <cuda_bf16.h>

#define NB 128
#define NU 16
#define NA 1024
#define NO 8
#define AT 64
#define NT (NA / AT)

// ---- persistent scratch (no allocations allowed) ----
// f_ll: [B][A][U][8]; S_gl: sum over u (unnormalized) [B][A][8];
// f_lg: mean over a [B][U][8]; f_gg: mean over u,a [B][8]. 3 ping-pong states.
__device__ float g_fll[3][(size_t)NB * NA * NU * NO];
__device__ float g_sgl[3][(size_t)NB * NA * NO];
__device__ float g_flg[3][NB * NU * NO];
__device__ float g_fgg[3][NB * NO];
__device__ float g_plg[NB * NT * NU * NO];   // per-tile partial sums for f_lg
__device__ float g_pgg[NB * NT * NO];        // per-tile partial sums for f_gg

__device__ __forceinline__ float frelu(float x) { return fmaxf(x, 0.0f); }

// =============================================================================
// Shared branch epilogue. v: per-thread inputs (4 points x CIN channels).
// sW layout: [4 branches][BSTR rows][8 outs]; ll rows = 0..CIN-1,
// (middle layers: lg rows 8..15, gl 16..23, gg 24..31 folded into sAddU/sAddA).
// =============================================================================
template <int CIN, int BSTR, bool ADDA>
__device__ __forceinline__ void branch_body(
    int b, int tile, int tid,
    const float (*v)[CIN],
    const float* __restrict__ sW,
    const float* __restrict__ sAddU,
    const float* __restrict__ sAddA,
    float* __restrict__ fll_out,
    float* __restrict__ sgl_out,
    float* __restrict__ sRedLg,
    float* __restrict__ sRedGg)
{
    const int u = tid & 15, alq = tid >> 4, warp = tid >> 5, lane = tid & 31;
    float acc_lg[8], acc_gg[8];
    #pragma unroll
    for (int o = 0; o < 8; o++) { acc_lg[o] = 0.0f; acc_gg[o] = 0.0f; }

    #pragma unroll
    for (int br = 0; br < 4; br++) {
        float au[8];
        #pragma unroll
        for (int o = 0; o < 8; o++) au[o] = sAddU[(br * 16 + u) * 8 + o];

        float z[4][8];
        #pragma unroll
        for (int i = 0; i < 4; i++) {
            #pragma unroll
            for (int o = 0; o < 8; o++) {
                float t = au[o];
                if (ADDA) t += sAddA[(br * 64 + alq + 16 * i) * 8 + o];
                z[i][o] = t;
            }
        }
        #pragma unroll
        for (int c = 0; c < CIN; c++) {
            const float* wr = &sW[(br * BSTR + c) * 8];
            float w0 = wr[0], w1 = wr[1], w2 = wr[2], w3 = wr[3];
            float w4 = wr[4], w5 = wr[5], w6 = wr[6], w7 = wr[7];
            #pragma unroll
            for (int i = 0; i < 4; i++) {
                float vc = v[i][c];
                z[i][0] = fmaf(vc, w0, z[i][0]);
                z[i][1] = fmaf(vc, w1, z[i][1]);
                z[i][2] = fmaf(vc, w2, z[i][2]);
                z[i][3] = fmaf(vc, w3, z[i][3]);
                z[i][4] = fmaf(vc, w4, z[i][4]);
                z[i][5] = fmaf(vc, w5, z[i][5]);
                z[i][6] = fmaf(vc, w6, z[i][6]);
                z[i][7] = fmaf(vc, w7, z[i][7]);
            }
        }
        if (br == 0) {                       // ll: pointwise write
            #pragma unroll
            for (int i = 0; i < 4; i++) {
                int a = tile * AT + alq + 16 * i;
                size_t idx = (((size_t)b * NA + a) * NU + u) * NO;
                float4 r0 = make_float4(frelu(z[i][0]), frelu(z[i][1]),
                                        frelu(z[i][2]), frelu(z[i][3]));
                float4 r1 = make_float4(frelu(z[i][4]), frelu(z[i][5]),
                                        frelu(z[i][6]), frelu(z[i][7]));
                *(float4*)(fll_out + idx)     = r0;
                *(float4*)(fll_out + idx + 4) = r1;
            }
        } else if (br == 1) {                // lg: accumulate over a
            #pragma unroll
            for (int i = 0; i < 4; i++)
                #pragma unroll
                for (int o = 0; o < 8; o++) acc_lg[o] += frelu(z[i][o]);
        } else if (br == 2) {                // gl: exact sum over u (in-warp)
            #pragma unroll
            for (int i = 0; i < 4; i++) {
                float s[8];
                #pragma unroll
                for (int o = 0; o < 8; o++) s[o] = frelu(z[i][o]);
                #pragma unroll
                for (int o = 0; o < 8; o++) {
                    s[o] += __shfl_xor_sync(0xffffffffu, s[o], 1, 16);
                    s[o] += __shfl_xor_sync(0xffffffffu, s[o], 2, 16);
                    s[o] += __shfl_xor_sync(0xffffffffu, s[o], 4, 16);
                    s[o] += __shfl_xor_sync(0xffffffffu, s[o], 8, 16);
                }
                if (u == 0) {
                    int a = tile * AT + alq + 16 * i;
                    size_t bs = ((size_t)b * NA + a) * NO;
                    *(float4*)(sgl_out + bs)     = make_float4(s[0], s[1], s[2], s[3]);
                    *(float4*)(sgl_out + bs + 4) = make_float4(s[4], s[5], s[6], s[7]);
                }
            }
        } else {                             // gg: accumulate over everything
            #pragma unroll
            for (int i = 0; i < 4; i++)
                #pragma unroll
                for (int o = 0; o < 8; o++) acc_gg[o] += frelu(z[i][o]);
        }
    }
    // lg: fold the two a-values sharing a u within the warp, stash per-warp
    #pragma unroll
    for (int o = 0; o < 8; o++)
        acc_lg[o] += __shfl_xor_sync(0xffffffffu, acc_lg[o], 16, 32);
    if (lane < 16) {
        #pragma unroll
        for (int o = 0; o < 8; o++) sRedLg[warp * 128 + u * 8 + o] = acc_lg[o];
    }
    // gg: full-warp butterfly
    #pragma unroll
    for (int o = 0; o < 8; o++) {
        acc_gg[o] += __shfl_xor_sync(0xffffffffu, acc_gg[o], 1);
        acc_gg[o] += __shfl_xor_sync(0xffffffffu, acc_gg[o], 2);
        acc_gg[o] += __shfl_xor_sync(0xffffffffu, acc_gg[o], 4);
        acc_gg[o] += __shfl_xor_sync(0xffffffffu, acc_gg[o], 8);
        acc_gg[o] += __shfl_xor_sync(0xffffffffu, acc_gg[o], 16);
    }
    if (lane == 0) {
        #pragma unroll
        for (int o = 0; o < 8; o++) sRedGg[warp * 8 + o] = acc_gg[o];
    }
}

__device__ __forceinline__ void write_partials(int b, int tile, int tid,
    const float* __restrict__ sRedLg, const float* __restrict__ sRedGg)
{
    if (tid < 128) {
        float s = 0.0f;
        #pragma unroll
        for (int w = 0; w < 8; w++) s += sRedLg[w * 128 + tid];
        g_plg[(b * NT + tile) * 128 + tid] = s;
    }
    if (tid < 8) {
        float s = 0.0f;
        #pragma unroll
        for (int w = 0; w < 8; w++) s += sRedGg[w * 8 + tid];
        g_pgg[(b * NT + tile) * 8 + tid] = s;
    }
}

// =============================================================================
// Layer 1: input = channel [B][4][U][A]
// =============================================================================
__global__ void __launch_bounds__(256)
k_layer1(const float* __restrict__ ch, const float* __restrict__ W1,
         const float* __restrict__ b1)
{
    __shared__ float sCh[4 * 16 * 65];     // padded to kill bank conflicts
    __shared__ float sW[128], sAddU[512];
    __shared__ float sRedLg[1024], sRedGg[64];
    const int tile = blockIdx.x, b = blockIdx.y, tid = threadIdx.x;

    for (int e = tid; e < 4096; e += 256) {
        int c = e >> 10, uu = (e >> 6) & 15, al = e & 63;
        sCh[c * 1040 + uu * 65 + al] =
            ch[(((size_t)b * 4 + c) * NU + uu) * NA + (size_t)tile * AT + al];
    }
    if (tid < 128) sW[tid] = W1[tid];
    #pragma unroll
    for (int k = 0; k < 2; k++) {
        int e = tid + 256 * k, br = e >> 7, o = e & 7;
        sAddU[e] = b1[br * 8 + o];
    }
    __syncthreads();

    const int u = tid & 15, alq = tid >> 4;
    float v[4][4];
    #pragma unroll
    for (int i = 0; i < 4; i++)
        #pragma unroll
        for (int c = 0; c < 4; c++)
            v[i][c] = sCh[c * 1040 + u * 65 + alq + 16 * i];

    branch_body<4, 4, false>(b, tile, tid, v, sW, sAddU, nullptr,
                             g_fll[0], g_sgl[0], sRedLg, sRedGg);
    __syncthreads();
    write_partials(b, tile, tid, sRedLg, sRedGg);
}

// =============================================================================
// Middle layers (2..7). W: [4][32][8], bias: [4][8].
// =============================================================================
template <bool SKIP>
__global__ void __launch_bounds__(256)
k_main(const float* __restrict__ W, const float* __restrict__ bias,
       int si, int si2, int so)
{
    __shared__ float sW[1024], sAddU[512], sAddA[2048];
    __shared__ float sSgl[512], sFlg[128], sFgg[8];
    __shared__ float sRedLg[1024], sRedGg[64];
    const int tile = blockIdx.x, b = blockIdx.y, tid = threadIdx.x;

    ((float4*)sW)[tid] = ((const float4*)W)[tid];
    if (tid < 128) {
        size_t base = ((size_t)b * NA + (size_t)tile * AT) * NO;
        float4 p = ((const float4*)(g_sgl[si] + base))[tid];
        if (SKIP) {
            float4 q = ((const float4*)(g_sgl[si2] + base))[tid];
            p.x = 0.5f * (p.x + q.x); p.y = 0.5f * (p.y + q.y);
            p.z = 0.5f * (p.z + q.z); p.w = 0.5f * (p.w + q.w);
        }
        ((float4*)sSgl)[tid] = p;
        float f = g_flg[si][b * 128 + tid];
        if (SKIP) f = 0.5f * (f + g_flg[si2][b * 128 + tid]);
        sFlg[tid] = f;
    }
    if (tid < 8) {
        float f = g_fgg[si][b * 8 + tid];
        if (SKIP) f = 0.5f * (f + g_fgg[si2][b * 8 + tid]);
        sFgg[tid] = f;
    }
    __syncthreads();

    // addU[br][u][o] = bias + W_lg^T f_lg(u) + W_gg^T f_gg
    #pragma unroll
    for (int k = 0; k < 2; k++) {
        int e = tid + 256 * k, br = e >> 7, uu = (e >> 3) & 15, o = e & 7;
        float acc = bias[br * 8 + o];
        #pragma unroll
        for (int c = 0; c < 8; c++) {
            acc += sFgg[c]          * sW[(br * 32 + 24 + c) * 8 + o];
            acc += sFlg[uu * 8 + c] * sW[(br * 32 +  8 + c) * 8 + o];
        }
        sAddU[e] = acc;
    }
    // addA[br][al][o] = (1/16) W_gl^T S_gl(a)
    #pragma unroll
    for (int k = 0; k < 8; k++) {
        int e = tid + 256 * k, br = e >> 9, al = (e >> 3) & 63, o = e & 7;
        float acc = 0.0f;
        #pragma unroll
        for (int c = 0; c < 8; c++)
            acc += sSgl[al * 8 + c] * sW[(br * 32 + 16 + c) * 8 + o];
        sAddA[e] = acc * (1.0f / 16.0f);
    }
    __syncthreads();

    const int u = tid & 15, alq = tid >> 4;
    const float* __restrict__ fin  = g_fll[si];
    const float* __restrict__ fin2 = g_fll[si2];
    float v[4][8];
    #pragma unroll
    for (int i = 0; i < 4; i++) {
        int a = tile * AT + alq + 16 * i;
        size_t idx = (((size_t)b * NA + a) * NU + u) * NO;
        float4 p0 = *(const float4*)(fin + idx);
        float4 p1 = *(const float4*)(fin + idx + 4);
        if (SKIP) {
            float4 q0 = *(const float4*)(fin2 + idx);
            float4 q1 = *(const float4*)(fin2 + idx + 4);
            p0.x = 0.5f * (p0.x + q0.x); p0.y = 0.5f * (p0.y + q0.y);
            p0.z = 0.5f * (p0.z + q0.z); p0.w = 0.5f * (p0.w + q0.w);
            p1.x = 0.5f * (p1.x + q1.x); p1.y = 0.5f * (p1.y + q1.y);
            p1.z = 0.5f * (p1.z + q1.z); p1.w = 0.5f * (p1.w + q1.w);
        }
        v[i][0] = p0.x; v[i][1] = p0.y; v[i][2] = p0.z; v[i][3] = p0.w;
        v[i][4] = p1.x; v[i][5] = p1.y; v[i][6] = p1.z; v[i][7] = p1.w;
    }

    branch_body<8, 32, true>(b, tile, tid, v, sW, sAddU, sAddA,
                             g_fll[so], g_sgl[so], sRedLg, sRedGg);
    __syncthreads();
    write_partials(b, tile, tid, sRedLg, sRedGg);
}

// =============================================================================
// Per-layer cross-tile reduction of lg/gg partials.
// =============================================================================
__global__ void k_reduce(int so)
{
    const int b = blockIdx.x, tid = threadIdx.x;
    if (tid < 128) {
        float s = 0.0f;
        #pragma unroll
        for (int t = 0; t < NT; t++) s += g_plg[(b * NT + t) * 128 + tid];
        g_flg[so][b * 128 + tid] = s * (1.0f / NA);
    }
    if (tid < 8) {
        float s = 0.0f;
        #pragma unroll
        for (int t = 0; t < NT; t++) s += g_pgg[(b * NT + t) * 8 + tid];
        g_fgg[so][b * 8 + tid] = s * (1.0f / (NA * NU));
    }
}

// =============================================================================
// Final: out[b, a] = pi * mean_u( conv(f_avg, W8) + b8 )
// =============================================================================
__global__ void __launch_bounds__(256)
k_final(const float* __restrict__ W8, const float* __restrict__ b8,
        float* __restrict__ out, int s1, int s2)
{
    __shared__ float sW8[32];
    __shared__ float cU[17];
    const int tile = blockIdx.x, b = blockIdx.y, tid = threadIdx.x;
    if (tid < 32) sW8[tid] = W8[tid];
    __syncthreads();
    if (tid < 16) {
        float s = 0.0f;
        #pragma unroll
        for (int c = 0; c < 8; c++)
            s += 0.5f * (g_flg[s1][b * 128 + tid * 8 + c] +
                         g_flg[s2][b * 128 + tid * 8 + c]) * sW8[8 + c];
        cU[tid] = s;
    }
    __syncthreads();
    if (tid == 0) {
        float s = 0.0f;
        for (int uu = 0; uu < 16; uu++) s += cU[uu];
        s *= (1.0f / 16.0f);
        #pragma unroll
        for (int c = 0; c < 8; c++)
            s += 0.5f * (g_fgg[s1][b * 8 + c] + g_fgg[s2][b * 8 + c]) * sW8[24 + c];
        s += b8[0];
        cU[16] = s;
    }
    __syncthreads();
    const float cb = cU[16];
    const int u = tid & 15, alq = tid >> 4;
    const float* __restrict__ f1 = g_fll[s1];
    const float* __restrict__ f2 = g_fll[s2];
    #pragma unroll
    for (int i = 0; i < 4; i++) {
        int a = tile * AT + alq + 16 * i;
        size_t idx = (((size_t)b * NA + a) * NU + u) * NO;
        float4 p0 = *(const float4*)(f1 + idx);
        float4 p1 = *(const float4*)(f1 + idx + 4);
        float4 q0 = *(const float4*)(f2 + idx);
        float4 q1 = *(const float4*)(f2 + idx + 4);
        float d = 0.0f;
        d += 0.5f * (p0.x + q0.x) * sW8[0];
        d += 0.5f * (p0.y + q0.y) * sW8[1];
        d += 0.5f * (p0.z + q0.z) * sW8[2];
        d += 0.5f * (p0.w + q0.w) * sW8[3];
        d += 0.5f * (p1.x + q1.x) * sW8[4];
        d += 0.5f * (p1.y + q1.y) * sW8[5];
        d += 0.5f * (p1.z + q1.z) * sW8[6];
        d += 0.5f * (p1.w + q1.w) * sW8[7];
        d += __shfl_xor_sync(0xffffffffu, d, 1, 16);
        d += __shfl_xor_sync(0xffffffffu, d, 2, 16);
        d += __shfl_xor_sync(0xffffffffu, d, 4, 16);
        d += __shfl_xor_sync(0xffffffffu, d, 8, 16);
        if (u == 0) {
            size_t bs = ((size_t)b * NA + a) * NO;
            float g = 0.0f;
            #pragma unroll
            for (int c = 0; c < 8; c++)
                g += 0.5f * (g_sgl[s1][bs + c] + g_sgl[s2][bs + c]) * sW8[16 + c];
            out[(size_t)b * NA + a] =
                3.14159265358979323846f * (d * (1.0f / 16.0f) + g * (1.0f / 16.0f) + cb);
        }
    }
}

// =============================================================================
extern "C" void kernel_launch(void* const* d_in, const int* in_sizes, int n_in,
                              void* d_out, int out_size)
{
    const float* channel = (const float*)d_in[0];
    const float* W1 = (const float*)d_in[1];
    const float* b1 = (const float*)d_in[2];
    const float* Wm = (const float*)d_in[3];
    const float* bm = (const float*)d_in[4];
    const float* W8 = (const float*)d_in[5];
    const float* b8 = (const float*)d_in[6];
    float* out = (float*)d_out;

    dim3 grd(NT, NB);
    // L1 -> s0 (= f1)
    k_layer1<<<grd, 256>>>(channel, W1, b1);
    k_reduce<<<NB, 128>>>(0);
    // L2: s0 -> s1
    k_main<false><<<grd, 256>>>(Wm + 0 * 1024, bm + 0 * 32, 0, 0, 1);
    k_reduce<<<NB, 128>>>(1);
    // L3: s1 -> s2 (= f3)
    k_main<false><<<grd, 256>>>(Wm + 1 * 1024, bm + 1 * 32, 1, 1, 2);
    k_reduce<<<NB, 128>>>(2);
    // L4: s2 -> s1
    k_main<false><<<grd, 256>>>(Wm + 2 * 1024, bm + 2 * 32, 2, 2, 1);
    k_reduce<<<NB, 128>>>(1);
    // L5: s1 -> s1 (in-place, per-point safe)
    k_main<false><<<grd, 256>>>(Wm + 3 * 1024, bm + 3 * 32, 1, 1, 1);
    k_reduce<<<NB, 128>>>(1);
    // L6: input (s1 + s0)/2 -> s0
    k_main<true><<<grd, 256>>>(Wm + 4 * 1024, bm + 4 * 32, 1, 0, 0);
    k_reduce<<<NB, 128>>>(0);
    // L7: s0 -> s0
    k_main<false><<<grd, 256>>>(Wm + 5 * 1024, bm + 5 * 32, 0, 0, 0);
    k_reduce<<<NB, 128>>>(0);
    // final: (s0 + s2)/2 -> out
    k_final<<<grd, 256>>>(W8, b8, out, 0, 2);
}

// round 3
// speedup vs baseline: 1.1528x; 1.1528x over previous
#include <cuda_runtime.h>
#include <cuda_bf16.h>

#define NB 128
#define NU 16
#define NA 1024
#define NO 8
#define AT 64
#define NT (NA / AT)

typedef unsigned long long u64;

// ---- persistent scratch (no allocations allowed) ----
// f_ll: [B][A][U][8]; S_gl: sum over u (unnormalized) [B][A][8]. 3 ping-pong states.
// plg/pgg: per-tile partial sums (cross-CTA read => 4 distinct slots, never in-place).
__device__ float g_fll[3][(size_t)NB * NA * NU * NO];
__device__ float g_sgl[3][(size_t)NB * NA * NO];
__device__ float g_plg[4][NB * NT * NU * NO];
__device__ float g_pgg[4][NB * NT * NO];

__device__ __forceinline__ float frelu(float x) { return fmaxf(x, 0.0f); }
__device__ __forceinline__ u64 pack2(float x) {
    u64 r; asm("mov.b64 %0, {%1, %1};" : "=l"(r) : "f"(x)); return r;
}
__device__ __forceinline__ float2 unpack2(u64 v) {
    float2 r; asm("mov.b64 {%0, %1}, %2;" : "=f"(r.x), "=f"(r.y) : "l"(v)); return r;
}
#define FMA2(d, a, b, c) asm("fma.rn.f32x2 %0, %1, %2, %3;" : "=l"(d) : "l"(a), "l"(b), "l"(c))
#define ADD2(d, a, b)    asm("add.rn.f32x2 %0, %1, %2;"     : "=l"(d) : "l"(a), "l"(b))

// =============================================================================
// Shared branch body. v: per-thread inputs (4 points x CIN channels).
// sW: [4 branches][BSTR rows][8 outs]. addU per (br,u), addA per (br,al).
// =============================================================================
template <int CIN, int BSTR, bool ADDA>
__device__ __forceinline__ void branch_body(
    int b, int tile, int tid, const float (*v)[CIN],
    const float* __restrict__ sW, const float* __restrict__ sAddU,
    const float* __restrict__ sAddA,
    float* __restrict__ fll_out, float* __restrict__ sgl_out,
    float* __restrict__ sRedLg, float* __restrict__ sRedGg)
{
    const int u = tid & 15, alq = tid >> 4, warp = tid >> 5, lane = tid & 31;
    float acc_lg[8], acc_gg[8];
    #pragma unroll
    for (int o = 0; o < 8; o++) { acc_lg[o] = 0.0f; acc_gg[o] = 0.0f; }

    #pragma unroll
    for (int br = 0; br < 4; br++) {
        const ulonglong2* aup = (const ulonglong2*)(sAddU + (br * 16 + u) * 8);
        const ulonglong2 au0 = aup[0], au1 = aup[1];
        u64 z2[4][4];
        #pragma unroll
        for (int i = 0; i < 4; i++) {
            if (ADDA) {
                const ulonglong2* ap =
                    (const ulonglong2*)(sAddA + (br * 64 + alq + 16 * i) * 8);
                ulonglong2 a0 = ap[0], a1 = ap[1];
                ADD2(z2[i][0], au0.x, a0.x);
                ADD2(z2[i][1], au0.y, a0.y);
                ADD2(z2[i][2], au1.x, a1.x);
                ADD2(z2[i][3], au1.y, a1.y);
            } else {
                z2[i][0] = au0.x; z2[i][1] = au0.y;
                z2[i][2] = au1.x; z2[i][3] = au1.y;
            }
        }
        #pragma unroll
        for (int c = 0; c < CIN; c++) {
            const ulonglong2* wp = (const ulonglong2*)(sW + (br * BSTR + c) * 8);
            const ulonglong2 w0 = wp[0], w1 = wp[1];
            #pragma unroll
            for (int i = 0; i < 4; i++) {
                u64 v2 = pack2(v[i][c]);
                FMA2(z2[i][0], v2, w0.x, z2[i][0]);
                FMA2(z2[i][1], v2, w0.y, z2[i][1]);
                FMA2(z2[i][2], v2, w1.x, z2[i][2]);
                FMA2(z2[i][3], v2, w1.y, z2[i][3]);
            }
        }
        #pragma unroll
        for (int i = 0; i < 4; i++) {
            float s[8];
            #pragma unroll
            for (int j = 0; j < 4; j++) {
                float2 p = unpack2(z2[i][j]);
                s[2 * j]     = frelu(p.x);
                s[2 * j + 1] = frelu(p.y);
            }
            if (br == 0) {                       // ll: pointwise write
                int a = tile * AT + alq + 16 * i;
                size_t idx = (((size_t)b * NA + a) * NU + u) * NO;
                *(float4*)(fll_out + idx)     = make_float4(s[0], s[1], s[2], s[3]);
                *(float4*)(fll_out + idx + 4) = make_float4(s[4], s[5], s[6], s[7]);
            } else if (br == 1) {                // lg: accumulate over a
                #pragma unroll
                for (int o = 0; o < 8; o++) acc_lg[o] += s[o];
            } else if (br == 2) {                // gl: tree-reduce over 16 u-lanes
                const bool h8 = (u & 8), h4 = (u & 4), h2 = (u & 2);
                float t4[4];
                #pragma unroll
                for (int j = 0; j < 4; j++) {
                    float send = h8 ? s[j] : s[j + 4];
                    float recv = __shfl_xor_sync(0xffffffffu, send, 8);
                    t4[j] = (h8 ? s[j + 4] : s[j]) + recv;
                }
                float t2[2];
                #pragma unroll
                for (int j = 0; j < 2; j++) {
                    float send = h4 ? t4[j] : t4[j + 2];
                    float recv = __shfl_xor_sync(0xffffffffu, send, 4);
                    t2[j] = (h4 ? t4[j + 2] : t4[j]) + recv;
                }
                float send = h2 ? t2[0] : t2[1];
                float recv = __shfl_xor_sync(0xffffffffu, send, 2);
                float t1 = (h2 ? t2[1] : t2[0]) + recv;
                t1 += __shfl_xor_sync(0xffffffffu, t1, 1);
                if (!(u & 1)) {
                    int o = (h8 ? 4 : 0) + (h4 ? 2 : 0) + (h2 ? 1 : 0);
                    int a = tile * AT + alq + 16 * i;
                    sgl_out[((size_t)b * NA + a) * NO + o] = t1;
                }
            } else {                             // gg
                #pragma unroll
                for (int o = 0; o < 8; o++) acc_gg[o] += s[o];
            }
        }
    }
    // lg: fold the two alq halves of the warp (xor 16); each lane keeps 4 values
    {
        const bool hA = (lane & 16);
        #pragma unroll
        for (int j = 0; j < 4; j++) {
            float send = hA ? acc_lg[j] : acc_lg[j + 4];
            float recv = __shfl_xor_sync(0xffffffffu, send, 16);
            float t = (hA ? acc_lg[j + 4] : acc_lg[j]) + recv;
            sRedLg[warp * 128 + u * 8 + (hA ? 4 : 0) + j] = t;
        }
    }
    // gg: tree-reduce 8 values over 32 lanes
    {
        const bool b0 = (lane & 1), b1 = (lane & 2), b2 = (lane & 4);
        float t4[4];
        #pragma unroll
        for (int j = 0; j < 4; j++) {
            float send = b0 ? acc_gg[j] : acc_gg[j + 4];
            float recv = __shfl_xor_sync(0xffffffffu, send, 1);
            t4[j] = (b0 ? acc_gg[j + 4] : acc_gg[j]) + recv;
        }
        float t2[2];
        #pragma unroll
        for (int j = 0; j < 2; j++) {
            float send = b1 ? t4[j] : t4[j + 2];
            float recv = __shfl_xor_sync(0xffffffffu, send, 2);
            t2[j] = (b1 ? t4[j + 2] : t4[j]) + recv;
        }
        float send = b2 ? t2[0] : t2[1];
        float recv = __shfl_xor_sync(0xffffffffu, send, 4);
        float t = (b2 ? t2[1] : t2[0]) + recv;
        t += __shfl_xor_sync(0xffffffffu, t, 8);
        t += __shfl_xor_sync(0xffffffffu, t, 16);
        if (lane < 8) {
            int o = (b0 ? 4 : 0) + (b1 ? 2 : 0) + (b2 ? 1 : 0);
            sRedGg[warp * 8 + o] = t;
        }
    }
}

__device__ __forceinline__ void write_partials(int b, int tile, int tid, int po,
    const float* __restrict__ sRedLg, const float* __restrict__ sRedGg)
{
    if (tid < 128) {
        float s = 0.0f;
        #pragma unroll
        for (int w = 0; w < 8; w++) s += sRedLg[w * 128 + tid];
        g_plg[po][(b * NT + tile) * 128 + tid] = s;
    }
    if (tid < 8) {
        float s = 0.0f;
        #pragma unroll
        for (int w = 0; w < 8; w++) s += sRedGg[w * 8 + tid];
        g_pgg[po][(b * NT + tile) * 8 + tid] = s;
    }
}

// =============================================================================
// Layer 1: input = channel [B][4][U][A]  ->  state 0, partials slot 0
// =============================================================================
__global__ void __launch_bounds__(256)
k_layer1(const float* __restrict__ ch, const float* __restrict__ W1,
         const float* __restrict__ b1)
{
    __shared__ float sCh[4 * 16 * 65];
    __shared__ float sW[128], sAddU[512];
    __shared__ float sRedLg[1024], sRedGg[64];
    const int tile = blockIdx.x, b = blockIdx.y, tid = threadIdx.x;

    for (int e = tid; e < 4096; e += 256) {
        int c = e >> 10, uu = (e >> 6) & 15, al = e & 63;
        sCh[c * 1040 + uu * 65 + al] =
            ch[(((size_t)b * 4 + c) * NU + uu) * NA + (size_t)tile * AT + al];
    }
    if (tid < 128) sW[tid] = W1[tid];
    #pragma unroll
    for (int k = 0; k < 2; k++) {
        int e = tid + 256 * k, br = e >> 7, o = e & 7;
        sAddU[e] = b1[br * 8 + o];
    }
    __syncthreads();

    const int u = tid & 15, alq = tid >> 4;
    float v[4][4];
    #pragma unroll
    for (int i = 0; i < 4; i++)
        #pragma unroll
        for (int c = 0; c < 4; c++)
            v[i][c] = sCh[c * 1040 + u * 65 + alq + 16 * i];

    branch_body<4, 4, false>(b, tile, tid, v, sW, sAddU, nullptr,
                             g_fll[0], g_sgl[0], sRedLg, sRedGg);
    __syncthreads();
    write_partials(b, tile, tid, 0, sRedLg, sRedGg);
}

// =============================================================================
// Middle layers (2..7). W: [4][32][8], bias: [4][8].
// si/si2/so: fll+sgl states; pi/pi2/po: plg/pgg slots (reduction fused here).
// =============================================================================
template <bool SKIP>
__global__ void __launch_bounds__(256)
k_main(const float* __restrict__ W, const float* __restrict__ bias,
       int si, int si2, int so, int pi, int pi2, int po)
{
    __shared__ float sW[1024], sAddU[512], sAddA[2048];
    __shared__ float sSgl[512], sFlg[128], sFgg[8];
    __shared__ float sRedLg[1024], sRedGg[64];
    const int tile = blockIdx.x, b = blockIdx.y, tid = threadIdx.x;

    ((float4*)sW)[tid] = ((const float4*)W)[tid];
    if (tid < 128) {
        size_t base = ((size_t)b * NA + (size_t)tile * AT) * NO;
        float4 p = ((const float4*)(g_sgl[si] + base))[tid];
        if (SKIP) {
            float4 q = ((const float4*)(g_sgl[si2] + base))[tid];
            p.x = 0.5f * (p.x + q.x); p.y = 0.5f * (p.y + q.y);
            p.z = 0.5f * (p.z + q.z); p.w = 0.5f * (p.w + q.w);
        }
        ((float4*)sSgl)[tid] = p;

        float s = 0.0f;
        #pragma unroll
        for (int t = 0; t < NT; t++) s += g_plg[pi][(b * NT + t) * 128 + tid];
        if (SKIP) {
            float s2 = 0.0f;
            #pragma unroll
            for (int t = 0; t < NT; t++) s2 += g_plg[pi2][(b * NT + t) * 128 + tid];
            s = 0.5f * (s + s2);
        }
        sFlg[tid] = s * (1.0f / NA);
    }
    if (tid < 8) {
        float s = 0.0f;
        #pragma unroll
        for (int t = 0; t < NT; t++) s += g_pgg[pi][(b * NT + t) * 8 + tid];
        if (SKIP) {
            float s2 = 0.0f;
            #pragma unroll
            for (int t = 0; t < NT; t++) s2 += g_pgg[pi2][(b * NT + t) * 8 + tid];
            s = 0.5f * (s + s2);
        }
        sFgg[tid] = s * (1.0f / (NA * NU));
    }
    __syncthreads();

    // addU[br][u][o] = bias + W_lg^T f_lg(u) + W_gg^T f_gg
    #pragma unroll
    for (int k = 0; k < 2; k++) {
        int e = tid + 256 * k, br = e >> 7, uu = (e >> 3) & 15, o = e & 7;
        float acc = bias[br * 8 + o];
        #pragma unroll
        for (int c = 0; c < 8; c++) {
            acc += sFgg[c]          * sW[(br * 32 + 24 + c) * 8 + o];
            acc += sFlg[uu * 8 + c] * sW[(br * 32 +  8 + c) * 8 + o];
        }
        sAddU[e] = acc;
    }
    // addA[br][al][o] = (1/16) W_gl^T S_gl(a)
    #pragma unroll
    for (int k = 0; k < 8; k++) {
        int e = tid + 256 * k, br = e >> 9, al = (e >> 3) & 63, o = e & 7;
        float acc = 0.0f;
        #pragma unroll
        for (int c = 0; c < 8; c++)
            acc += sSgl[al * 8 + c] * sW[(br * 32 + 16 + c) * 8 + o];
        sAddA[e] = acc * (1.0f / 16.0f);
    }
    __syncthreads();

    const int u = tid & 15, alq = tid >> 4;
    const float* __restrict__ fin  = g_fll[si];
    const float* __restrict__ fin2 = g_fll[si2];
    float v[4][8];
    #pragma unroll
    for (int i = 0; i < 4; i++) {
        int a = tile * AT + alq + 16 * i;
        size_t idx = (((size_t)b * NA + a) * NU + u) * NO;
        float4 p0 = *(const float4*)(fin + idx);
        float4 p1 = *(const float4*)(fin + idx + 4);
        if (SKIP) {
            float4 q0 = *(const float4*)(fin2 + idx);
            float4 q1 = *(const float4*)(fin2 + idx + 4);
            p0.x = 0.5f * (p0.x + q0.x); p0.y = 0.5f * (p0.y + q0.y);
            p0.z = 0.5f * (p0.z + q0.z); p0.w = 0.5f * (p0.w + q0.w);
            p1.x = 0.5f * (p1.x + q1.x); p1.y = 0.5f * (p1.y + q1.y);
            p1.z = 0.5f * (p1.z + q1.z); p1.w = 0.5f * (p1.w + q1.w);
        }
        v[i][0] = p0.x; v[i][1] = p0.y; v[i][2] = p0.z; v[i][3] = p0.w;
        v[i][4] = p1.x; v[i][5] = p1.y; v[i][6] = p1.z; v[i][7] = p1.w;
    }

    branch_body<8, 32, true>(b, tile, tid, v, sW, sAddU, sAddA,
                             g_fll[so], g_sgl[so], sRedLg, sRedGg);
    __syncthreads();
    write_partials(b, tile, tid, po, sRedLg, sRedGg);
}

// =============================================================================
// Final: out[b, a] = pi * mean_u( conv(f_avg, W8) + b8 )
// =============================================================================
__global__ void __launch_bounds__(256)
k_final(const float* __restrict__ W8, const float* __restrict__ b8,
        float* __restrict__ out, int s1, int s2, int p1, int p2)
{
    __shared__ float sW8[32];
    __shared__ float sFlg[128], sFgg[8];
    __shared__ float cU[17];
    const int tile = blockIdx.x, b = blockIdx.y, tid = threadIdx.x;
    if (tid < 32) sW8[tid] = W8[tid];
    if (tid < 128) {
        float s = 0.0f;
        #pragma unroll
        for (int t = 0; t < NT; t++)
            s += g_plg[p1][(b * NT + t) * 128 + tid] +
                 g_plg[p2][(b * NT + t) * 128 + tid];
        sFlg[tid] = s * (0.5f / NA);
    }
    if (tid < 8) {
        float s = 0.0f;
        #pragma unroll
        for (int t = 0; t < NT; t++)
            s += g_pgg[p1][(b * NT + t) * 8 + tid] +
                 g_pgg[p2][(b * NT + t) * 8 + tid];
        sFgg[tid] = s * (0.5f / (NA * NU));
    }
    __syncthreads();
    if (tid < 16) {
        float s = 0.0f;
        #pragma unroll
        for (int c = 0; c < 8; c++)
            s += sFlg[tid * 8 + c] * sW8[8 + c];
        cU[tid] = s;
    }
    __syncthreads();
    if (tid == 0) {
        float s = 0.0f;
        for (int uu = 0; uu < 16; uu++) s += cU[uu];
        s *= (1.0f / 16.0f);
        #pragma unroll
        for (int c = 0; c < 8; c++) s += sFgg[c] * sW8[24 + c];
        s += b8[0];
        cU[16] = s;
    }
    __syncthreads();
    const float cb = cU[16];
    const int u = tid & 15, alq = tid >> 4;
    const float* __restrict__ f1 = g_fll[s1];
    const float* __restrict__ f2 = g_fll[s2];
    #pragma unroll
    for (int i = 0; i < 4; i++) {
        int a = tile * AT + alq + 16 * i;
        size_t idx = (((size_t)b * NA + a) * NU + u) * NO;
        float4 p0 = *(const float4*)(f1 + idx);
        float4 p1 = *(const float4*)(f1 + idx + 4);
        float4 q0 = *(const float4*)(f2 + idx);
        float4 q1 = *(const float4*)(f2 + idx + 4);
        float d = 0.0f;
        d += 0.5f * (p0.x + q0.x) * sW8[0];
        d += 0.5f * (p0.y + q0.y) * sW8[1];
        d += 0.5f * (p0.z + q0.z) * sW8[2];
        d += 0.5f * (p0.w + q0.w) * sW8[3];
        d += 0.5f * (p1.x + q1.x) * sW8[4];
        d += 0.5f * (p1.y + q1.y) * sW8[5];
        d += 0.5f * (p1.z + q1.z) * sW8[6];
        d += 0.5f * (p1.w + q1.w) * sW8[7];
        d += __shfl_xor_sync(0xffffffffu, d, 1, 16);
        d += __shfl_xor_sync(0xffffffffu, d, 2, 16);
        d += __shfl_xor_sync(0xffffffffu, d, 4, 16);
        d += __shfl_xor_sync(0xffffffffu, d, 8, 16);
        if (u == 0) {
            size_t bs = ((size_t)b * NA + a) * NO;
            float g = 0.0f;
            #pragma unroll
            for (int c = 0; c < 8; c++)
                g += 0.5f * (g_sgl[s1][bs + c] + g_sgl[s2][bs + c]) * sW8[16 + c];
            out[(size_t)b * NA + a] =
                3.14159265358979323846f * (d * (1.0f / 16.0f) + g * (1.0f / 16.0f) + cb);
        }
    }
}

// =============================================================================
extern "C" void kernel_launch(void* const* d_in, const int* in_sizes, int n_in,
                              void* d_out, int out_size)
{
    const float* channel = (const float*)d_in[0];
    const float* W1 = (const float*)d_in[1];
    const float* b1 = (const float*)d_in[2];
    const float* Wm = (const float*)d_in[3];
    const float* bm = (const float*)d_in[4];
    const float* W8 = (const float*)d_in[5];
    const float* b8 = (const float*)d_in[6];
    float* out = (float*)d_out;

    dim3 grd(NT, NB);
    // L1 -> fll s0 (= f1), plg p0
    k_layer1<<<grd, 256>>>(channel, W1, b1);
    // L2: s0/p0 -> s1/p1
    k_main<false><<<grd, 256>>>(Wm + 0 * 1024, bm + 0 * 32, 0, 0, 1, 0, 0, 1);
    // L3: s1/p1 -> s2/p2 (= f3)
    k_main<false><<<grd, 256>>>(Wm + 1 * 1024, bm + 1 * 32, 1, 1, 2, 1, 1, 2);
    // L4: s2/p2 -> s1/p1
    k_main<false><<<grd, 256>>>(Wm + 2 * 1024, bm + 2 * 32, 2, 2, 1, 2, 2, 1);
    // L5: s1/p1 -> s1/p3 (fll in-place per-point safe; plg to fresh slot)
    k_main<false><<<grd, 256>>>(Wm + 3 * 1024, bm + 3 * 32, 1, 1, 1, 1, 1, 3);
    // L6: skip with f1: (s1+s0)/2, (p3+p0)/2 -> s0/p1
    k_main<true><<<grd, 256>>>(Wm + 4 * 1024, bm + 4 * 32, 1, 0, 0, 3, 0, 1);
    // L7: s0/p1 -> s0/p0
    k_main<false><<<grd, 256>>>(Wm + 5 * 1024, bm + 5 * 32, 0, 0, 0, 1, 1, 0);
    // final: average of states (s0, s2) / plg slots (p0, p2)
    k_final<<<grd, 256>>>(W8, b8, out, 0, 2, 0, 2);
}